// round 10
// baseline (speedup 1.0000x reference)
#include <cuda_runtime.h>
#include <math.h>

#define BB 2
#define SS 128
#define HH 256
#define CC 8
#define PAD 260        // main-kernel smem row stride (floats, multiple of 4)

// ---------------- scratch (device globals; no allocation allowed) ----------
__device__ float g_z[BB * SS * HH];            // 256 KB
__device__ float g_e[BB * CC * SS];            // 8 KB   [b][c][s]
__device__ float g_cumexp[BB * SS * CC];       // 8 KB   [b][s][c]
__device__ float g_cumm[BB * SS * CC * HH];    // 2 MB   [b][s][c][h]

// ---------------- packed f32x2 helpers (sm_100a; ptxas never emits these) --
union F2U { float2 f; unsigned long long u; };

__device__ __forceinline__ void pk_add(F2U& d, const F2U& a, const F2U& b) {
    asm("add.rn.f32x2 %0, %1, %2;" : "=l"(d.u) : "l"(a.u), "l"(b.u));
}
__device__ __forceinline__ void pk_fma(F2U& d, const F2U& a, const F2U& b,
                                       const F2U& c) {
    asm("fma.rn.f32x2 %0, %1, %2, %3;" : "=l"(d.u) : "l"(a.u), "l"(b.u), "l"(c.u));
}

// ---------------------------------------------------------------------------
// Kernel A: z[b,s,h] = relu(memory[b,s,:] . W_w[h,:] + W_b[h])
// grid 256 = (32 s-tiles of 8 rows) x (8 h-tiles of 32); 256 threads.
// ---------------------------------------------------------------------------
__global__ void __launch_bounds__(256) kernelA(const float* __restrict__ memory,
                                               const float* __restrict__ Ww,
                                               const float* __restrict__ Wb)
{
    __shared__ float Msh[8 * HH];    // 8 KB

    int bid = blockIdx.x;
    int st = bid >> 3;               // s-tile 0..31
    int ht = bid & 7;                // h-tile 0..7
    int s0 = st * 8;
    int tid = threadIdx.x;
    int lane = tid & 31, w = tid >> 5;

#pragma unroll
    for (int t = 0; t < 2; t++) {
        int idx = tid + t * 256;
        int rr = idx >> 6;
        int k4 = idx & 63;
        ((float4*)&Msh[rr * HH])[k4] =
            ((const float4*)&memory[(s0 + rr) * HH])[k4];
    }
    __syncthreads();

    int hl = lane >> 3;              // 0..3
    int kp = lane & 7;               // 0..7
    int h = ht * 32 + w * 4 + hl;

    float acc[8];
#pragma unroll
    for (int r = 0; r < 8; r++) acc[r] = 0.0f;

    const float4* wr = (const float4*)&Ww[h * HH];
#pragma unroll
    for (int i = 0; i < 8; i++) {
        float4 wv = wr[i * 8 + kp];          // coalesced across kp
#pragma unroll
        for (int r = 0; r < 8; r++) {
            float4 m = *(const float4*)&Msh[r * HH + i * 32 + kp * 4];
            acc[r] = fmaf(m.x, wv.x,
                     fmaf(m.y, wv.y,
                     fmaf(m.z, wv.z,
                     fmaf(m.w, wv.w, acc[r]))));
        }
    }

#pragma unroll
    for (int r = 0; r < 8; r++) {
        float v = acc[r];
        v += __shfl_xor_sync(0xffffffffu, v, 1);
        v += __shfl_xor_sync(0xffffffffu, v, 2);
        v += __shfl_xor_sync(0xffffffffu, v, 4);
        acc[r] = v;
    }
    if (kp == 0) {
        float bias = Wb[h];
#pragma unroll
        for (int r = 0; r < 8; r++)
            g_z[(s0 + r) * HH + h] = fmaxf(acc[r] + bias, 0.0f);
    }
}

// ---------------------------------------------------------------------------
// Kernel B1: per (b,c): score, softmax-exp, cumsum -> g_cumexp; e -> g_e.
// grid 16 = B*C, 128 threads.
// ---------------------------------------------------------------------------
__global__ void __launch_bounds__(128) kernelB1(const float* __restrict__ Uw)
{
    __shared__ float Ush[HH];
    __shared__ float wred[4];
    __shared__ float wsum[4];

    int b = blockIdx.x >> 3;
    int c = blockIdx.x & 7;
    int tid = threadIdx.x;
    int lane = tid & 31, w = tid >> 5;

    if (tid < 64)
        ((float4*)Ush)[tid] = ((const float4*)(Uw + c * HH))[tid];
    __syncthreads();

    float sc = 0.0f;
    {
        const float4* zr = (const float4*)&g_z[(b * SS + tid) * HH];
        const float4* u4 = (const float4*)Ush;
#pragma unroll 8
        for (int k = 0; k < 64; k++) {
            float4 z = zr[k];
            float4 u = u4[k];
            sc += z.x * u.x + z.y * u.y + z.z * u.z + z.w * u.w;
        }
    }
    float m = sc;
#pragma unroll
    for (int o = 16; o > 0; o >>= 1)
        m = fmaxf(m, __shfl_xor_sync(0xffffffffu, m, o));
    if (lane == 0) wred[w] = m;
    __syncthreads();
    float mx = fmaxf(fmaxf(wred[0], wred[1]), fmaxf(wred[2], wred[3]));

    float e = expf(sc - mx);
    float x = e;
#pragma unroll
    for (int o = 1; o < 32; o <<= 1) {
        float t = __shfl_up_sync(0xffffffffu, x, o);
        if (lane >= o) x += t;
    }
    if (lane == 31) wsum[w] = x;
    __syncthreads();
    float pre = 0.0f;
    for (int ww = 0; ww < w; ww++) pre += wsum[ww];

    g_e[(b * CC + c) * SS + tid] = e;
    g_cumexp[(b * SS + tid) * CC + c] = x + pre;
}

// ---------------------------------------------------------------------------
// Kernel B2: g_cumm[b,s,c,h] = inclusive cumsum_s( memory[b,s,h] * e[b,c,s] )
// grid 128 = (b,c) x 8 h-chunks of 32; 256 threads.
// ---------------------------------------------------------------------------
__global__ void __launch_bounds__(256) kernelB2(const float* __restrict__ memory)
{
    __shared__ float esh[SS];
    __shared__ float psum[8][32];

    int bid = blockIdx.x;
    int hc = bid & 7;
    int bc = bid >> 3;               // b*CC + c
    int b = bc >> 3;
    int c = bc & 7;
    int tid = threadIdx.x;
    int hl = tid & 31;
    int sg = tid >> 5;               // s-group 0..7

    if (tid < SS) esh[tid] = g_e[bc * SS + tid];
    __syncthreads();

    int h = hc * 32 + hl;
    const float* mp = memory + (size_t)b * SS * HH + h;

    float val[16];
    float run = 0.0f;
#pragma unroll
    for (int k = 0; k < 16; k++) {
        int s = sg * 16 + k;
        run = fmaf(mp[(size_t)s * HH], esh[s], run);
        val[k] = run;
    }
    psum[sg][hl] = run;
    __syncthreads();

    float off = 0.0f;
    for (int t = 0; t < sg; t++) off += psum[t][hl];

    float* op = g_cumm + ((size_t)b * SS * CC + c) * HH + h;
#pragma unroll
    for (int k = 0; k < 16; k++) {
        int s = sg * 16 + k;
        op[(size_t)s * (CC * HH)] = val[k] + off;
    }
}

// ---------------------------------------------------------------------------
// Main kernel (packed f32x2):
//   out[b,i,j,c] = (sum_h relu(R[j,h] + negP[i,h]) * V[c,h]) / denom + V_b[c]
// grid 512 = b(2) x i-tile(8 of 16) x j-tile(8 of 16) x c-pair(4); 256 thr.
// warps: 2 local c x 4 h-quarters; lanes: 8 ilane x 4 jlane; tile 2i x 4j.
// P staged NEGATED so the packed op is add.rn.f32x2 (+fma.rn.f32x2).
// Core stream per 2 elems: FADD2 + 2 FMNMX + FFMA2 (was 2 FADD+2 FMNMX+2 FFMA).
// cumexp epilogue loads issued BEFORE compute (latency hidden).
// ---------------------------------------------------------------------------
__global__ void __launch_bounds__(256, 2) kernelMain(const float* __restrict__ Vw,
                                                     const float* __restrict__ Vb,
                                                     float* __restrict__ out)
{
    extern __shared__ float sm[];
    float* Psh = sm;                   // 32 * PAD = 8320 (negated)
    float* Rsh = sm + 8320;            // 8320
    float* Vsh = sm + 16640;           // 512   (total 17152 fl = 68608 B)
    float* red = sm;                   // aliases Psh (2048 fl; P dead by then)

    int bid = blockIdx.x;
    int cpair = bid & 3;
    int jt = (bid >> 2) & 7;
    int it = (bid >> 5) & 7;
    int b = bid >> 8;
    int i0 = it * 16, j0 = jt * 16, cbase = cpair * 2;
    int tid = threadIdx.x;

    // stage V (2 c x 256 h)
    if (tid < 128)
        *(float4*)&Vsh[tid * 4] = *(const float4*)&Vw[cbase * HH + tid * 4];

    // stage negated-P and R tiles: 32 rows each (2c x 16)
    {
        int rr = tid >> 3;             // 0..31
        int c4 = tid & 7;
        int cl = rr >> 4, ir = rr & 15;
        int gi = i0 + ir;
        int gj = j0 + ir;
        const float* srcR = &g_cumm[((size_t)(b * SS + gj) * CC + cbase + cl) * HH];
        const float* srcP = (gi == 0) ? (const float*)0
            : &g_cumm[((size_t)(b * SS + gi - 1) * CC + cbase + cl) * HH];
        float* dstR = &Rsh[rr * PAD];
        float* dstP = &Psh[rr * PAD];
#pragma unroll
        for (int k = 0; k < 8; k++) {
            int h = c4 * 4 + k * 32;
            *(float4*)&dstR[h] = *(const float4*)&srcR[h];
            float4 pv = srcP ? *(const float4*)&srcP[h]
                             : make_float4(0.f, 0.f, 0.f, 0.f);
            pv.x = -pv.x; pv.y = -pv.y; pv.z = -pv.z; pv.w = -pv.w;
            *(float4*)&dstP[h] = pv;
        }
    }
    __syncthreads();

    // epilogue operands loaded EARLY (latency hidden under compute)
    int ei = tid >> 4, ej = tid & 15;
    int gie = i0 + ei, gje = j0 + ej;
    float cej0 = g_cumexp[(b * SS + gje) * CC + cbase];
    float cej1 = g_cumexp[(b * SS + gje) * CC + cbase + 1];
    float cei0 = 0.0f, cei1 = 0.0f;
    if (gie > 0) {
        cei0 = g_cumexp[(b * SS + gie - 1) * CC + cbase];
        cei1 = g_cumexp[(b * SS + gie - 1) * CC + cbase + 1];
    }
    float vb0 = Vb[cbase], vb1 = Vb[cbase + 1];

    int lane = tid & 31, w = tid >> 5;
    int cl = w & 1;                    // local c
    int hq = w >> 1;                   // h quarter 0..3
    int ilane = lane >> 2;             // 0..7
    int jlane = lane & 3;              // 0..3

    const float* Pb = &Psh[(cl * 16) * PAD];
    const float* Rb = &Rsh[(cl * 16) * PAD];
    const float* Vp = &Vsh[cl * HH];

    F2U acc[2][4];
#pragma unroll
    for (int ii = 0; ii < 2; ii++)
#pragma unroll
        for (int jj = 0; jj < 4; jj++) {
            acc[ii][jj].f.x = 0.0f;
            acc[ii][jj].f.y = 0.0f;
        }

    int hbase = hq * 64;
#pragma unroll 4
    for (int hh = 0; hh < 64; hh += 4) {
        int h = hbase + hh;
        float4 v  = *(const float4*)&Vp[h];
        float4 p0 = *(const float4*)&Pb[ilane * PAD + h];
        float4 p1 = *(const float4*)&Pb[(ilane + 8) * PAD + h];
        F2U v01, v23, p0a, p0b, p1a, p1b;
        v01.f = make_float2(v.x, v.y);   v23.f = make_float2(v.z, v.w);
        p0a.f = make_float2(p0.x, p0.y); p0b.f = make_float2(p0.z, p0.w);
        p1a.f = make_float2(p1.x, p1.y); p1b.f = make_float2(p1.z, p1.w);
#pragma unroll
        for (int jj = 0; jj < 4; jj++) {
            float4 r = *(const float4*)&Rb[(jlane + 4 * jj) * PAD + h];
            F2U r01, r23, t;
            r01.f = make_float2(r.x, r.y);
            r23.f = make_float2(r.z, r.w);
            pk_add(t, r01, p0a);
            t.f.x = fmaxf(t.f.x, 0.0f); t.f.y = fmaxf(t.f.y, 0.0f);
            pk_fma(acc[0][jj], t, v01, acc[0][jj]);
            pk_add(t, r23, p0b);
            t.f.x = fmaxf(t.f.x, 0.0f); t.f.y = fmaxf(t.f.y, 0.0f);
            pk_fma(acc[0][jj], t, v23, acc[0][jj]);
            pk_add(t, r01, p1a);
            t.f.x = fmaxf(t.f.x, 0.0f); t.f.y = fmaxf(t.f.y, 0.0f);
            pk_fma(acc[1][jj], t, v01, acc[1][jj]);
            pk_add(t, r23, p1b);
            t.f.x = fmaxf(t.f.x, 0.0f); t.f.y = fmaxf(t.f.y, 0.0f);
            pk_fma(acc[1][jj], t, v23, acc[1][jj]);
        }
    }

    __syncthreads();   // all warps done reading Psh before red overwrites it

    // write h-quarter partials (red aliases Psh)
#pragma unroll
    for (int ii = 0; ii < 2; ii++)
#pragma unroll
        for (int jj = 0; jj < 4; jj++) {
            int i = ilane + 8 * ii;
            int j = jlane + 4 * jj;
            red[hq * 512 + cl * 256 + i * 16 + j] = acc[ii][jj].f.x + acc[ii][jj].f.y;
        }
    __syncthreads();

    // epilogue: thread tid handles (c0, c1) for one (i,j)
    {
        int o = ei * 16 + ej;
        float s0 = red[o] + red[512 + o] + red[1024 + o] + red[1536 + o];
        int o2 = o + 256;
        float s1 = red[o2] + red[512 + o2] + red[1024 + o2] + red[1536 + o2];
        float d0 = cej0 - cei0; if (d0 <= 1e-6f) d0 = 100.0f;
        float d1 = cej1 - cei1; if (d1 <= 1e-6f) d1 = 100.0f;
        float2 res;
        res.x = __fdividef(s0, d0) + vb0;
        res.y = __fdividef(s1, d1) + vb1;
        *(float2*)&out[((size_t)(b * SS + gie) * SS + gje) * CC + cbase] = res;
    }
}

// ---------------------------------------------------------------------------
extern "C" void kernel_launch(void* const* d_in, const int* in_sizes, int n_in,
                              void* d_out, int out_size)
{
    (void)in_sizes; (void)n_in; (void)out_size;
    const float* memory = (const float*)d_in[0];
    const float* Ww     = (const float*)d_in[1];
    const float* Wb     = (const float*)d_in[2];
    const float* Uw     = (const float*)d_in[3];
    const float* Vw     = (const float*)d_in[4];
    const float* Vb     = (const float*)d_in[5];
    float* out          = (float*)d_out;

    cudaFuncSetAttribute(kernelMain, cudaFuncAttributeMaxDynamicSharedMemorySize,
                         17152 * 4);

    kernelA<<<256, 256>>>(memory, Ww, Wb);
    kernelB1<<<16, 128>>>(Uw);
    kernelB2<<<128, 256>>>(memory);
    kernelMain<<<512, 256, 17152 * 4>>>(Vw, Vb, out);
}

// round 11
// speedup vs baseline: 1.0010x; 1.0010x over previous
#include <cuda_runtime.h>
#include <math.h>

#define BB 2
#define SS 128
#define HH 256
#define CC 8
#define PAD 260        // main-kernel smem row stride (floats, multiple of 4)

// ---------------- scratch (device globals; no allocation allowed) ----------
__device__ float g_z[BB * SS * HH];            // 256 KB
__device__ float g_e[BB * CC * SS];            // 8 KB   [b][c][s]
__device__ float g_cumexp[BB * SS * CC];       // 8 KB   [b][s][c]
__device__ float g_cumm[BB * SS * CC * HH];    // 2 MB   [b][s][c][h]

// ---------------- packed f32x2 helpers (sm_100a; ptxas never emits these) --
union F2U { float2 f; unsigned long long u; };

__device__ __forceinline__ void pk_add(F2U& d, const F2U& a, const F2U& b) {
    asm("add.rn.f32x2 %0, %1, %2;" : "=l"(d.u) : "l"(a.u), "l"(b.u));
}
__device__ __forceinline__ void pk_fma(F2U& d, const F2U& a, const F2U& b,
                                       const F2U& c) {
    asm("fma.rn.f32x2 %0, %1, %2, %3;" : "=l"(d.u) : "l"(a.u), "l"(b.u), "l"(c.u));
}

// ---------------------------------------------------------------------------
// Kernel A: z[b,s,h] = relu(memory[b,s,:] . W_w[h,:] + W_b[h])
// grid 256 = (32 s-tiles of 8 rows) x (8 h-tiles of 32); 256 threads.
// ---------------------------------------------------------------------------
__global__ void __launch_bounds__(256) kernelA(const float* __restrict__ memory,
                                               const float* __restrict__ Ww,
                                               const float* __restrict__ Wb)
{
    __shared__ float Msh[8 * HH];    // 8 KB

    int bid = blockIdx.x;
    int st = bid >> 3;               // s-tile 0..31
    int ht = bid & 7;                // h-tile 0..7
    int s0 = st * 8;
    int tid = threadIdx.x;
    int lane = tid & 31, w = tid >> 5;

#pragma unroll
    for (int t = 0; t < 2; t++) {
        int idx = tid + t * 256;
        int rr = idx >> 6;
        int k4 = idx & 63;
        ((float4*)&Msh[rr * HH])[k4] =
            ((const float4*)&memory[(s0 + rr) * HH])[k4];
    }
    __syncthreads();

    int hl = lane >> 3;              // 0..3
    int kp = lane & 7;               // 0..7
    int h = ht * 32 + w * 4 + hl;

    float acc[8];
#pragma unroll
    for (int r = 0; r < 8; r++) acc[r] = 0.0f;

    const float4* wr = (const float4*)&Ww[h * HH];
#pragma unroll
    for (int i = 0; i < 8; i++) {
        float4 wv = wr[i * 8 + kp];          // coalesced across kp
#pragma unroll
        for (int r = 0; r < 8; r++) {
            float4 m = *(const float4*)&Msh[r * HH + i * 32 + kp * 4];
            acc[r] = fmaf(m.x, wv.x,
                     fmaf(m.y, wv.y,
                     fmaf(m.z, wv.z,
                     fmaf(m.w, wv.w, acc[r]))));
        }
    }

#pragma unroll
    for (int r = 0; r < 8; r++) {
        float v = acc[r];
        v += __shfl_xor_sync(0xffffffffu, v, 1);
        v += __shfl_xor_sync(0xffffffffu, v, 2);
        v += __shfl_xor_sync(0xffffffffu, v, 4);
        acc[r] = v;
    }
    if (kp == 0) {
        float bias = Wb[h];
#pragma unroll
        for (int r = 0; r < 8; r++)
            g_z[(s0 + r) * HH + h] = fmaxf(acc[r] + bias, 0.0f);
    }
}

// ---------------------------------------------------------------------------
// Kernel B1: per (b,c): score, softmax-exp, cumsum -> g_cumexp; e -> g_e.
// grid 16 = B*C, 128 threads.
// ---------------------------------------------------------------------------
__global__ void __launch_bounds__(128) kernelB1(const float* __restrict__ Uw)
{
    __shared__ float Ush[HH];
    __shared__ float wred[4];
    __shared__ float wsum[4];

    int b = blockIdx.x >> 3;
    int c = blockIdx.x & 7;
    int tid = threadIdx.x;
    int lane = tid & 31, w = tid >> 5;

    if (tid < 64)
        ((float4*)Ush)[tid] = ((const float4*)(Uw + c * HH))[tid];
    __syncthreads();

    float sc = 0.0f;
    {
        const float4* zr = (const float4*)&g_z[(b * SS + tid) * HH];
        const float4* u4 = (const float4*)Ush;
#pragma unroll 8
        for (int k = 0; k < 64; k++) {
            float4 z = zr[k];
            float4 u = u4[k];
            sc += z.x * u.x + z.y * u.y + z.z * u.z + z.w * u.w;
        }
    }
    float m = sc;
#pragma unroll
    for (int o = 16; o > 0; o >>= 1)
        m = fmaxf(m, __shfl_xor_sync(0xffffffffu, m, o));
    if (lane == 0) wred[w] = m;
    __syncthreads();
    float mx = fmaxf(fmaxf(wred[0], wred[1]), fmaxf(wred[2], wred[3]));

    float e = expf(sc - mx);
    float x = e;
#pragma unroll
    for (int o = 1; o < 32; o <<= 1) {
        float t = __shfl_up_sync(0xffffffffu, x, o);
        if (lane >= o) x += t;
    }
    if (lane == 31) wsum[w] = x;
    __syncthreads();
    float pre = 0.0f;
    for (int ww = 0; ww < w; ww++) pre += wsum[ww];

    g_e[(b * CC + c) * SS + tid] = e;
    g_cumexp[(b * SS + tid) * CC + c] = x + pre;
}

// ---------------------------------------------------------------------------
// Kernel B2: g_cumm[b,s,c,h] = inclusive cumsum_s( memory[b,s,h] * e[b,c,s] )
// grid 128 = (b,c) x 8 h-chunks of 32; 256 threads.
// ---------------------------------------------------------------------------
__global__ void __launch_bounds__(256) kernelB2(const float* __restrict__ memory)
{
    __shared__ float esh[SS];
    __shared__ float psum[8][32];

    int bid = blockIdx.x;
    int hc = bid & 7;
    int bc = bid >> 3;               // b*CC + c
    int b = bc >> 3;
    int c = bc & 7;
    int tid = threadIdx.x;
    int hl = tid & 31;
    int sg = tid >> 5;               // s-group 0..7

    if (tid < SS) esh[tid] = g_e[bc * SS + tid];
    __syncthreads();

    int h = hc * 32 + hl;
    const float* mp = memory + (size_t)b * SS * HH + h;

    float val[16];
    float run = 0.0f;
#pragma unroll
    for (int k = 0; k < 16; k++) {
        int s = sg * 16 + k;
        run = fmaf(mp[(size_t)s * HH], esh[s], run);
        val[k] = run;
    }
    psum[sg][hl] = run;
    __syncthreads();

    float off = 0.0f;
    for (int t = 0; t < sg; t++) off += psum[t][hl];

    float* op = g_cumm + ((size_t)b * SS * CC + c) * HH + h;
#pragma unroll
    for (int k = 0; k < 16; k++) {
        int s = sg * 16 + k;
        op[(size_t)s * (CC * HH)] = val[k] + off;
    }
}

// ---------------------------------------------------------------------------
// Main kernel (c-split for occupancy, packed f32x2):
//   out[b,i,j,c] = (sum_h relu(R[j,h] + negP[i,h]) * V[c,h]) / denom + V_b[c]
// grid 1024 = b(2) x i-tile(8 of 16) x j-tile(8 of 16) x c(8); 128 threads.
// 4 warps = 4 h-quarters; lanes 8 ilane x 4 jlane; per-lane tile 2i x 4j.
// smem 34.3 KB static -> 6 CTAs/SM = 24 warps (vs 16): latency-bound fix.
// ---------------------------------------------------------------------------
__global__ void __launch_bounds__(128, 6) kernelMain(const float* __restrict__ Vw,
                                                     const float* __restrict__ Vb,
                                                     float* __restrict__ out)
{
    __shared__ float Psh[16 * PAD];    // 4160 fl (negated P)
    __shared__ float Rsh[16 * PAD];    // 4160 fl
    __shared__ float Vsh[HH];          // 256 fl   (total 8576 fl = 34304 B)
    float* red = Psh;                  // alias; 4*264=1056 fl, P dead by then

    int bid = blockIdx.x;
    int c  = bid & 7;
    int jt = (bid >> 3) & 7;
    int it = (bid >> 6) & 7;
    int b  = bid >> 9;
    int i0 = it * 16, j0 = jt * 16;
    int tid = threadIdx.x;

    // stage V (1 c x 256 h)
    if (tid < 64)
        ((float4*)Vsh)[tid] = ((const float4*)(Vw + c * HH))[tid];

    // stage negated-P and R tiles: 16 rows each, 8 threads/row
    {
        int rr = tid >> 3;             // 0..15
        int c8 = tid & 7;
        int gi = i0 + rr;
        int gj = j0 + rr;
        const float* srcR = &g_cumm[((size_t)(b * SS + gj) * CC + c) * HH];
        const float* srcP = (gi == 0) ? (const float*)0
            : &g_cumm[((size_t)(b * SS + gi - 1) * CC + c) * HH];
        float* dstR = &Rsh[rr * PAD];
        float* dstP = &Psh[rr * PAD];
#pragma unroll
        for (int k = 0; k < 8; k++) {
            int h = c8 * 4 + k * 32;
            *(float4*)&dstR[h] = *(const float4*)&srcR[h];
            float4 pv = srcP ? *(const float4*)&srcP[h]
                             : make_float4(0.f, 0.f, 0.f, 0.f);
            pv.x = -pv.x; pv.y = -pv.y; pv.z = -pv.z; pv.w = -pv.w;
            *(float4*)&dstP[h] = pv;
        }
    }
    __syncthreads();

    // epilogue operands loaded EARLY (latency hidden under compute);
    // thread handles (i,j) pairs tid and tid+128
    float cej[2], cei[2];
#pragma unroll
    for (int rep = 0; rep < 2; rep++) {
        int idx = tid + rep * 128;
        int gie = i0 + (idx >> 4), gje = j0 + (idx & 15);
        cej[rep] = g_cumexp[(b * SS + gje) * CC + c];
        cei[rep] = (gie > 0) ? g_cumexp[(b * SS + gie - 1) * CC + c] : 0.0f;
    }
    float vb = Vb[c];

    int lane = tid & 31;
    int hq = tid >> 5;                 // h quarter 0..3
    int ilane = lane >> 2;             // 0..7
    int jlane = lane & 3;              // 0..3

    F2U acc[2][4];
#pragma unroll
    for (int ii = 0; ii < 2; ii++)
#pragma unroll
        for (int jj = 0; jj < 4; jj++) {
            acc[ii][jj].f.x = 0.0f;
            acc[ii][jj].f.y = 0.0f;
        }

    int hbase = hq * 64;
#pragma unroll 4
    for (int hh = 0; hh < 64; hh += 4) {
        int h = hbase + hh;
        float4 v  = *(const float4*)&Vsh[h];
        float4 p0 = *(const float4*)&Psh[ilane * PAD + h];
        float4 p1 = *(const float4*)&Psh[(ilane + 8) * PAD + h];
        F2U v01, v23, p0a, p0b, p1a, p1b;
        v01.f = make_float2(v.x, v.y);   v23.f = make_float2(v.z, v.w);
        p0a.f = make_float2(p0.x, p0.y); p0b.f = make_float2(p0.z, p0.w);
        p1a.f = make_float2(p1.x, p1.y); p1b.f = make_float2(p1.z, p1.w);
#pragma unroll
        for (int jj = 0; jj < 4; jj++) {
            float4 r = *(const float4*)&Rsh[(jlane + 4 * jj) * PAD + h];
            F2U r01, r23, t;
            r01.f = make_float2(r.x, r.y);
            r23.f = make_float2(r.z, r.w);
            pk_add(t, r01, p0a);
            t.f.x = fmaxf(t.f.x, 0.0f); t.f.y = fmaxf(t.f.y, 0.0f);
            pk_fma(acc[0][jj], t, v01, acc[0][jj]);
            pk_add(t, r23, p0b);
            t.f.x = fmaxf(t.f.x, 0.0f); t.f.y = fmaxf(t.f.y, 0.0f);
            pk_fma(acc[0][jj], t, v23, acc[0][jj]);
            pk_add(t, r01, p1a);
            t.f.x = fmaxf(t.f.x, 0.0f); t.f.y = fmaxf(t.f.y, 0.0f);
            pk_fma(acc[1][jj], t, v01, acc[1][jj]);
            pk_add(t, r23, p1b);
            t.f.x = fmaxf(t.f.x, 0.0f); t.f.y = fmaxf(t.f.y, 0.0f);
            pk_fma(acc[1][jj], t, v23, acc[1][jj]);
        }
    }

    __syncthreads();   // all warps done reading Psh before red overwrites it

    // write h-quarter partials (red aliases Psh); stride 264 per hq
#pragma unroll
    for (int ii = 0; ii < 2; ii++)
#pragma unroll
        for (int jj = 0; jj < 4; jj++) {
            int i = ilane + 8 * ii;
            int j = jlane + 4 * jj;
            red[hq * 264 + i * 16 + j] = acc[ii][jj].f.x + acc[ii][jj].f.y;
        }
    __syncthreads();

    // epilogue: thread tid handles (i,j) pairs tid and tid+128
#pragma unroll
    for (int rep = 0; rep < 2; rep++) {
        int idx = tid + rep * 128;
        int i = idx >> 4, j = idx & 15;
        int o = i * 16 + j;
        float s = red[o] + red[264 + o] + red[528 + o] + red[792 + o];
        float d = cej[rep] - cei[rep]; if (d <= 1e-6f) d = 100.0f;
        int gi = i0 + i, gj = j0 + j;
        out[((size_t)(b * SS + gi) * SS + gj) * CC + c] = __fdividef(s, d) + vb;
    }
}

// ---------------------------------------------------------------------------
extern "C" void kernel_launch(void* const* d_in, const int* in_sizes, int n_in,
                              void* d_out, int out_size)
{
    (void)in_sizes; (void)n_in; (void)out_size;
    const float* memory = (const float*)d_in[0];
    const float* Ww     = (const float*)d_in[1];
    const float* Wb     = (const float*)d_in[2];
    const float* Uw     = (const float*)d_in[3];
    const float* Vw     = (const float*)d_in[4];
    const float* Vb     = (const float*)d_in[5];
    float* out          = (float*)d_out;

    kernelA<<<256, 256>>>(memory, Ww, Wb);
    kernelB1<<<16, 128>>>(Uw);
    kernelB2<<<128, 256>>>(memory);
    kernelMain<<<1024, 128>>>(Vw, Vb, out);
}

// round 13
// speedup vs baseline: 1.3333x; 1.3320x over previous
#include <cuda_runtime.h>
#include <math.h>

#define BB 2
#define SS 128
#define HH 256
#define CC 8
#define PAD 260        // main-kernel smem row stride (floats, multiple of 4)

// ---------------- scratch (device globals; no allocation allowed) ----------
__device__ float g_scorep[256 * 64];           // 64 KB  [bidA][c*8+sl]
__device__ float g_e[BB * CC * SS];            // 8 KB   [b][c][s]
__device__ float g_cumexp[BB * SS * CC];       // 8 KB   [b][s][c]
__device__ float g_cumm[BB * SS * CC * HH];    // 2 MB   [b][s][c][h]

// ---------------- packed f32x2 helpers (sm_100a) ---------------------------
union F2U { float2 f; unsigned long long u; };

__device__ __forceinline__ void pk_add(F2U& d, const F2U& a, const F2U& b) {
    asm("add.rn.f32x2 %0, %1, %2;" : "=l"(d.u) : "l"(a.u), "l"(b.u));
}
__device__ __forceinline__ void pk_fma(F2U& d, const F2U& a, const F2U& b,
                                       const F2U& c) {
    asm("fma.rn.f32x2 %0, %1, %2, %3;" : "=l"(d.u) : "l"(a.u), "l"(b.u), "l"(c.u));
}

// ---------------------------------------------------------------------------
// Kernel A: z = relu(memory . W^T + Wb) kept ON-CHIP; emits partial scores
//   g_scorep[bid][c*8+sl] = sum_{h in tile} U[c,h] * z[s0+sl, h]
// grid 256 = (32 s-tiles of 8 rows) x (8 h-tiles of 32); 256 threads.
// ---------------------------------------------------------------------------
__global__ void __launch_bounds__(256, 2) kernelA(const float* __restrict__ memory,
                                                  const float* __restrict__ Ww,
                                                  const float* __restrict__ Wb,
                                                  const float* __restrict__ Uw)
{
    __shared__ float Msh[8 * HH];    // 8 KB
    __shared__ float zsh[8][33];     // 8 s-rows x 32 h (pad 33)

    int bid = blockIdx.x;
    int st = bid >> 3;               // s-tile 0..31
    int ht = bid & 7;                // h-tile 0..7
    int s0 = st * 8;
    int tid = threadIdx.x;
    int lane = tid & 31, w = tid >> 5;

#pragma unroll
    for (int t = 0; t < 2; t++) {
        int idx = tid + t * 256;
        int rr = idx >> 6;
        int k4 = idx & 63;
        ((float4*)&Msh[rr * HH])[k4] =
            ((const float4*)&memory[(s0 + rr) * HH])[k4];
    }
    __syncthreads();

    int hl = lane >> 3;              // 0..3
    int kp = lane & 7;               // 0..7
    int h = ht * 32 + w * 4 + hl;

    // preload all 8 W vectors -> guaranteed MLP=8 on the LDGs
    float4 wv[8];
    const float4* wr = (const float4*)&Ww[h * HH];
#pragma unroll
    for (int i = 0; i < 8; i++) wv[i] = wr[i * 8 + kp];

    float acc[8];
#pragma unroll
    for (int r = 0; r < 8; r++) acc[r] = 0.0f;

#pragma unroll
    for (int i = 0; i < 8; i++) {
#pragma unroll
        for (int r = 0; r < 8; r++) {
            float4 m = *(const float4*)&Msh[r * HH + i * 32 + kp * 4];
            acc[r] = fmaf(m.x, wv[i].x,
                     fmaf(m.y, wv[i].y,
                     fmaf(m.z, wv[i].z,
                     fmaf(m.w, wv[i].w, acc[r]))));
        }
    }

#pragma unroll
    for (int r = 0; r < 8; r++) {
        float v = acc[r];
        v += __shfl_xor_sync(0xffffffffu, v, 1);
        v += __shfl_xor_sync(0xffffffffu, v, 2);
        v += __shfl_xor_sync(0xffffffffu, v, 4);
        acc[r] = v;
    }
    if (kp == 0) {
        float bias = Wb[h];
#pragma unroll
        for (int r = 0; r < 8; r++)
            zsh[r][w * 4 + hl] = fmaxf(acc[r] + bias, 0.0f);
    }
    __syncthreads();

    // partial scores: 64 threads, c = t>>3, sl = t&7; 32-long dot
    if (tid < 64) {
        int c = tid >> 3, sl = tid & 7;
        const float4* ur = (const float4*)(Uw + c * HH + ht * 32);
        float p = 0.0f;
#pragma unroll
        for (int k = 0; k < 8; k++) {
            float4 u = ur[k];
            p += u.x * zsh[sl][k * 4]     + u.y * zsh[sl][k * 4 + 1]
               + u.z * zsh[sl][k * 4 + 2] + u.w * zsh[sl][k * 4 + 3];
        }
        g_scorep[bid * 64 + tid] = p;
    }
}

// ---------------------------------------------------------------------------
// Kernel B1 (slim): per (b,c): score[s] = sum_ht scorep; softmax-exp; scan.
// grid 16 = B*C, 128 threads.
// ---------------------------------------------------------------------------
__global__ void __launch_bounds__(128) kernelB1()
{
    __shared__ float wred[4];
    __shared__ float wsum[4];

    int b = blockIdx.x >> 3;
    int c = blockIdx.x & 7;
    int tid = threadIdx.x;
    int lane = tid & 31, w = tid >> 5;

    int grow = b * SS + tid;         // global row
    int st = grow >> 3, sl = grow & 7;
    float sc = 0.0f;
#pragma unroll
    for (int ht = 0; ht < 8; ht++)
        sc += g_scorep[(st * 8 + ht) * 64 + c * 8 + sl];

    float m = sc;
#pragma unroll
    for (int o = 16; o > 0; o >>= 1)
        m = fmaxf(m, __shfl_xor_sync(0xffffffffu, m, o));
    if (lane == 0) wred[w] = m;
    __syncthreads();
    float mx = fmaxf(fmaxf(wred[0], wred[1]), fmaxf(wred[2], wred[3]));

    float e = expf(sc - mx);
    float x = e;
#pragma unroll
    for (int o = 1; o < 32; o <<= 1) {
        float t = __shfl_up_sync(0xffffffffu, x, o);
        if (lane >= o) x += t;
    }
    if (lane == 31) wsum[w] = x;
    __syncthreads();
    float pre = 0.0f;
    for (int ww = 0; ww < w; ww++) pre += wsum[ww];

    g_e[(b * CC + c) * SS + tid] = e;
    g_cumexp[(b * SS + tid) * CC + c] = x + pre;
}

// ---------------------------------------------------------------------------
// Kernel B2: g_cumm[b,s,c,h] = inclusive cumsum_s( memory[b,s,h] * e[b,c,s] )
// grid 128 = (b,c) x 8 h-chunks of 32; 256 threads.
// ---------------------------------------------------------------------------
__global__ void __launch_bounds__(256) kernelB2(const float* __restrict__ memory)
{
    __shared__ float esh[SS];
    __shared__ float psum[8][32];

    int bid = blockIdx.x;
    int hc = bid & 7;
    int bc = bid >> 3;               // b*CC + c
    int b = bc >> 3;
    int c = bc & 7;
    int tid = threadIdx.x;
    int hl = tid & 31;
    int sg = tid >> 5;               // s-group 0..7

    if (tid < SS) esh[tid] = g_e[bc * SS + tid];
    __syncthreads();

    int h = hc * 32 + hl;
    const float* mp = memory + (size_t)b * SS * HH + h;

    float val[16];
    float run = 0.0f;
#pragma unroll
    for (int k = 0; k < 16; k++) {
        int s = sg * 16 + k;
        run = fmaf(mp[(size_t)s * HH], esh[s], run);
        val[k] = run;
    }
    psum[sg][hl] = run;
    __syncthreads();

    float off = 0.0f;
    for (int t = 0; t < sg; t++) off += psum[t][hl];

    float* op = g_cumm + ((size_t)b * SS * CC + c) * HH + h;
#pragma unroll
    for (int k = 0; k < 16; k++) {
        int s = sg * 16 + k;
        op[(size_t)s * (CC * HH)] = val[k] + off;
    }
}

// ---------------------------------------------------------------------------
// Main kernel (c-split, packed f32x2, phase-friendly lane map):
//   out[b,i,j,c] = (sum_h relu(R[j,h] + negP[i,h]) * V[c,h]) / denom + V_b[c]
// grid 1024 = b(2) x i-tile(8 of 16) x j-tile(8 of 16) x c(8); 128 threads.
// ---------------------------------------------------------------------------
__global__ void __launch_bounds__(128, 6) kernelMain(const float* __restrict__ Vw,
                                                     const float* __restrict__ Vb,
                                                     float* __restrict__ out)
{
    __shared__ float Psh[16 * PAD];    // 4160 fl (negated P)
    __shared__ float Rsh[16 * PAD];    // 4160 fl
    __shared__ float Vsh[HH];          // 256 fl   (total 34304 B)
    float* red = Psh;                  // alias; P dead by reduction time

    int bid = blockIdx.x;
    int c  = bid & 7;
    int jt = (bid >> 3) & 7;
    int it = (bid >> 6) & 7;
    int b  = bid >> 9;
    int i0 = it * 16, j0 = jt * 16;
    int tid = threadIdx.x;

    if (tid < 64)
        ((float4*)Vsh)[tid] = ((const float4*)(Vw + c * HH))[tid];

    // stage negated-P and R tiles: 16 rows each, 8 threads/row
    {
        int rr = tid >> 3;             // 0..15
        int c8 = tid & 7;
        int gi = i0 + rr;
        int gj = j0 + rr;
        const float* srcR = &g_cumm[((size_t)(b * SS + gj) * CC + c) * HH];
        const float* srcP = (gi == 0) ? (const float*)0
            : &g_cumm[((size_t)(b * SS + gi - 1) * CC + c) * HH];
        float* dstR = &Rsh[rr * PAD];
        float* dstP = &Psh[rr * PAD];
#pragma unroll
        for (int k = 0; k < 8; k++) {
            int h = c8 * 4 + k * 32;
            *(float4*)&dstR[h] = *(const float4*)&srcR[h];
            float4 pv = srcP ? *(const float4*)&srcP[h]
                             : make_float4(0.f, 0.f, 0.f, 0.f);
            pv.x = -pv.x; pv.y = -pv.y; pv.z = -pv.z; pv.w = -pv.w;
            *(float4*)&dstP[h] = pv;
        }
    }
    __syncthreads();

    // epilogue operands loaded EARLY
    float cej[2], cei[2];
#pragma unroll
    for (int rep = 0; rep < 2; rep++) {
        int idx = tid + rep * 128;
        int gie = i0 + (idx >> 4), gje = j0 + (idx & 15);
        cej[rep] = g_cumexp[(b * SS + gje) * CC + c];
        cei[rep] = (gie > 0) ? g_cumexp[(b * SS + gie - 1) * CC + c] : 0.0f;
    }
    float vb = Vb[c];

    int lane = tid & 31;
    int hq = tid >> 5;                 // h quarter 0..3
    int ilane = lane & 7;              // 0..7  (phase-major)
    int jlane = lane >> 3;             // 0..3

    F2U acc[2][4];
#pragma unroll
    for (int ii = 0; ii < 2; ii++)
#pragma unroll
        for (int jj = 0; jj < 4; jj++) {
            acc[ii][jj].f.x = 0.0f;
            acc[ii][jj].f.y = 0.0f;
        }

    int hbase = hq * 64;
#pragma unroll 4
    for (int hh = 0; hh < 64; hh += 4) {
        int h = hbase + hh;
        float4 v  = *(const float4*)&Vsh[h];
        float4 p0 = *(const float4*)&Psh[ilane * PAD + h];
        float4 p1 = *(const float4*)&Psh[(ilane + 8) * PAD + h];
        F2U v01, v23, p0a, p0b, p1a, p1b;
        v01.f = make_float2(v.x, v.y);   v23.f = make_float2(v.z, v.w);
        p0a.f = make_float2(p0.x, p0.y); p0b.f = make_float2(p0.z, p0.w);
        p1a.f = make_float2(p1.x, p1.y); p1b.f = make_float2(p1.z, p1.w);
#pragma unroll
        for (int jj = 0; jj < 4; jj++) {
            float4 r = *(const float4*)&Rsh[(jlane + 4 * jj) * PAD + h];
            F2U r01, r23, t;
            r01.f = make_float2(r.x, r.y);
            r23.f = make_float2(r.z, r.w);
            pk_add(t, r01, p0a);
            t.f.x = fmaxf(t.f.x, 0.0f); t.f.y = fmaxf(t.f.y, 0.0f);
            pk_fma(acc[0][jj], t, v01, acc[0][jj]);
            pk_add(t, r23, p0b);
            t.f.x = fmaxf(t.f.x, 0.0f); t.f.y = fmaxf(t.f.y, 0.0f);
            pk_fma(acc[0][jj], t, v23, acc[0][jj]);
            pk_add(t, r01, p1a);
            t.f.x = fmaxf(t.f.x, 0.0f); t.f.y = fmaxf(t.f.y, 0.0f);
            pk_fma(acc[1][jj], t, v01, acc[1][jj]);
            pk_add(t, r23, p1b);
            t.f.x = fmaxf(t.f.x, 0.0f); t.f.y = fmaxf(t.f.y, 0.0f);
            pk_fma(acc[1][jj], t, v23, acc[1][jj]);
        }
    }

    __syncthreads();   // all warps done reading Psh before red overwrites it

#pragma unroll
    for (int ii = 0; ii < 2; ii++)
#pragma unroll
        for (int jj = 0; jj < 4; jj++) {
            int i = ilane + 8 * ii;
            int j = jlane + 4 * jj;
            red[hq * 264 + i * 16 + j] = acc[ii][jj].f.x + acc[ii][jj].f.y;
        }
    __syncthreads();

#pragma unroll
    for (int rep = 0; rep < 2; rep++) {
        int idx = tid + rep * 128;
        int i = idx >> 4, j = idx & 15;
        int o = i * 16 + j;
        float s = red[o] + red[264 + o] + red[528 + o] + red[792 + o];
        float d = cej[rep] - cei[rep]; if (d <= 1e-6f) d = 100.0f;
        int gi = i0 + i, gj = j0 + j;
        out[((size_t)(b * SS + gi) * SS + gj) * CC + c] = __fdividef(s, d) + vb;
    }
}

// ---------------------------------------------------------------------------
extern "C" void kernel_launch(void* const* d_in, const int* in_sizes, int n_in,
                              void* d_out, int out_size)
{
    (void)in_sizes; (void)n_in; (void)out_size;
    const float* memory = (const float*)d_in[0];
    const float* Ww     = (const float*)d_in[1];
    const float* Wb     = (const float*)d_in[2];
    const float* Uw     = (const float*)d_in[3];
    const float* Vw     = (const float*)d_in[4];
    const float* Vb     = (const float*)d_in[5];
    float* out          = (float*)d_out;

    kernelA<<<256, 256>>>(memory, Ww, Wb, Uw);
    kernelB1<<<16, 128>>>();
    kernelB2<<<128, 256>>>(memory);
    kernelMain<<<1024, 128>>>(Vw, Vb, out);
}

// round 15
// speedup vs baseline: 1.4525x; 1.0894x over previous
#include <cuda_runtime.h>
#include <math.h>

#define BB 2
#define SS 128
#define HH 256
#define CC 8
#define PAD 260        // main-kernel smem row stride (floats, multiple of 4)

// ---------------- scratch (device globals; no allocation allowed) ----------
__device__ float g_scorep[256 * 64];           // 64 KB  [bidA][c*8+sl]
__device__ float g_cumexp[BB * SS * CC];       // 8 KB   [b][s][c]
__device__ float g_cumm[BB * SS * CC * HH];    // 2 MB   [b][s][c][h]

// ---------------- packed f32x2 helpers (sm_100a) ---------------------------
// NOTE: only add/mul/fma exist in the f32x2 SIMD set; max.f32x2 does NOT
// (ptxas round-14 failure). relu stays scalar FMNMX.
union F2U { float2 f; unsigned long long u; };

__device__ __forceinline__ void pk_add(F2U& d, const F2U& a, const F2U& b) {
    asm("add.rn.f32x2 %0, %1, %2;" : "=l"(d.u) : "l"(a.u), "l"(b.u));
}
__device__ __forceinline__ void pk_fma(F2U& d, const F2U& a, const F2U& b,
                                       const F2U& c) {
    asm("fma.rn.f32x2 %0, %1, %2, %3;" : "=l"(d.u) : "l"(a.u), "l"(b.u), "l"(c.u));
}

// ---------------------------------------------------------------------------
// Kernel A: z = relu(memory . W^T + Wb) kept ON-CHIP; emits partial scores
//   g_scorep[bid][c*8+sl] = sum_{h in tile} U[c,h] * z[s0+sl, h]
// grid 256 = (32 s-tiles of 8 rows) x (8 h-tiles of 32); 256 threads.
// ---------------------------------------------------------------------------
__global__ void __launch_bounds__(256, 2) kernelA(const float* __restrict__ memory,
                                                  const float* __restrict__ Ww,
                                                  const float* __restrict__ Wb,
                                                  const float* __restrict__ Uw)
{
    __shared__ float Msh[8 * HH];    // 8 KB
    __shared__ float zsh[8][33];     // 8 s-rows x 32 h (pad 33)

    int bid = blockIdx.x;
    int st = bid >> 3;               // s-tile 0..31
    int ht = bid & 7;                // h-tile 0..7
    int s0 = st * 8;
    int tid = threadIdx.x;
    int lane = tid & 31, w = tid >> 5;

#pragma unroll
    for (int t = 0; t < 2; t++) {
        int idx = tid + t * 256;
        int rr = idx >> 6;
        int k4 = idx & 63;
        ((float4*)&Msh[rr * HH])[k4] =
            ((const float4*)&memory[(s0 + rr) * HH])[k4];
    }
    __syncthreads();

    int hl = lane >> 3;              // 0..3
    int kp = lane & 7;               // 0..7
    int h = ht * 32 + w * 4 + hl;

    // preload all 8 W vectors -> guaranteed MLP=8 on the LDGs
    float4 wv[8];
    const float4* wr = (const float4*)&Ww[h * HH];
#pragma unroll
    for (int i = 0; i < 8; i++) wv[i] = wr[i * 8 + kp];

    float acc[8];
#pragma unroll
    for (int r = 0; r < 8; r++) acc[r] = 0.0f;

#pragma unroll
    for (int i = 0; i < 8; i++) {
#pragma unroll
        for (int r = 0; r < 8; r++) {
            float4 m = *(const float4*)&Msh[r * HH + i * 32 + kp * 4];
            acc[r] = fmaf(m.x, wv[i].x,
                     fmaf(m.y, wv[i].y,
                     fmaf(m.z, wv[i].z,
                     fmaf(m.w, wv[i].w, acc[r]))));
        }
    }

#pragma unroll
    for (int r = 0; r < 8; r++) {
        float v = acc[r];
        v += __shfl_xor_sync(0xffffffffu, v, 1);
        v += __shfl_xor_sync(0xffffffffu, v, 2);
        v += __shfl_xor_sync(0xffffffffu, v, 4);
        acc[r] = v;
    }
    if (kp == 0) {
        float bias = Wb[h];
#pragma unroll
        for (int r = 0; r < 8; r++)
            zsh[r][w * 4 + hl] = fmaxf(acc[r] + bias, 0.0f);
    }
    __syncthreads();

    // partial scores: 64 threads, c = t>>3, sl = t&7; 32-long dot
    if (tid < 64) {
        int c = tid >> 3, sl = tid & 7;
        const float4* ur = (const float4*)(Uw + c * HH + ht * 32);
        float p = 0.0f;
#pragma unroll
        for (int k = 0; k < 8; k++) {
            float4 u = ur[k];
            p += u.x * zsh[sl][k * 4]     + u.y * zsh[sl][k * 4 + 1]
               + u.z * zsh[sl][k * 4 + 2] + u.w * zsh[sl][k * 4 + 3];
        }
        g_scorep[bid * 64 + tid] = p;
    }
}

// ---------------------------------------------------------------------------
// Kernel B (fused B1+B2): grid 128 = (b,c) x 8 h-chunks; 256 threads.
// Phase 1 (tid<128): score[s] = sum_ht scorep (L2-hot, 64KB total); softmax-
//   exp; warp scan. Duplicated across the 8 h-chunk blocks of one (b,c) —
//   ~1k loads, trivial. cumexp stored by hc==0 blocks only.
// Phase 2 (all 256): cumm for 32 h-lanes x 8 s-groups of 16.
// ---------------------------------------------------------------------------
__global__ void __launch_bounds__(256) kernelB(const float* __restrict__ memory)
{
    __shared__ float esh[SS];
    __shared__ float wred[4];
    __shared__ float wsum[4];
    __shared__ float psum[8][32];

    int bid = blockIdx.x;
    int hc = bid & 7;
    int bc = bid >> 3;               // b*CC + c
    int b = bc >> 3;
    int c = bc & 7;
    int tid = threadIdx.x;
    int lane = tid & 31, w = tid >> 5;

    // Phase 1a: score + warp max (warps 0..3)
    float sc = 0.0f;
    if (tid < SS) {
        int grow = b * SS + tid;
        int st = grow >> 3, sl = grow & 7;
#pragma unroll
        for (int ht = 0; ht < 8; ht++)
            sc += g_scorep[(st * 8 + ht) * 64 + c * 8 + sl];
        float m = sc;
#pragma unroll
        for (int o = 16; o > 0; o >>= 1)
            m = fmaxf(m, __shfl_xor_sync(0xffffffffu, m, o));
        if (lane == 0) wred[w] = m;
    }
    __syncthreads();

    // Phase 1b: exp + warp scan; e -> esh
    float x = 0.0f;
    if (tid < SS) {
        float mx = fmaxf(fmaxf(wred[0], wred[1]), fmaxf(wred[2], wred[3]));
        float e = expf(sc - mx);
        x = e;
#pragma unroll
        for (int o = 1; o < 32; o <<= 1) {
            float t = __shfl_up_sync(0xffffffffu, x, o);
            if (lane >= o) x += t;
        }
        if (lane == 31) wsum[w] = x;
        esh[tid] = e;
    }
    __syncthreads();

    // Phase 1c: cumexp store (hc==0 blocks only)
    if (hc == 0 && tid < SS) {
        float pre = 0.0f;
        for (int ww = 0; ww < w; ww++) pre += wsum[ww];
        g_cumexp[(b * SS + tid) * CC + c] = x + pre;
    }

    // Phase 2: cumm
    {
        int hl = tid & 31;
        int sg = tid >> 5;           // s-group 0..7
        int h = hc * 32 + hl;
        const float* mp = memory + (size_t)b * SS * HH + h;

        float val[16];
        float run = 0.0f;
#pragma unroll
        for (int k = 0; k < 16; k++) {
            int s = sg * 16 + k;
            run = fmaf(mp[(size_t)s * HH], esh[s], run);
            val[k] = run;
        }
        psum[sg][hl] = run;
        __syncthreads();

        float off = 0.0f;
        for (int t = 0; t < sg; t++) off += psum[t][hl];

        float* op = g_cumm + ((size_t)b * SS * CC + c) * HH + h;
#pragma unroll
        for (int k = 0; k < 16; k++) {
            int s = sg * 16 + k;
            op[(size_t)s * (CC * HH)] = val[k] + off;
        }
    }
}

// ---------------------------------------------------------------------------
// Main kernel (c-split, packed add/fma f32x2, scalar FMNMX relu):
//   out[b,i,j,c] = (sum_h relu(R[j,h] + negP[i,h]) * V[c,h]) / denom + V_b[c]
// grid 1024 = b(2) x i-tile(8 of 16) x j-tile(8 of 16) x c(8); 128 threads.
// ---------------------------------------------------------------------------
__global__ void __launch_bounds__(128, 6) kernelMain(const float* __restrict__ Vw,
                                                     const float* __restrict__ Vb,
                                                     float* __restrict__ out)
{
    __shared__ float Psh[16 * PAD];    // 4160 fl (negated P)
    __shared__ float Rsh[16 * PAD];    // 4160 fl
    __shared__ float Vsh[HH];          // 256 fl   (total 34304 B)
    float* red = Psh;                  // alias; P dead by reduction time

    int bid = blockIdx.x;
    int c  = bid & 7;
    int jt = (bid >> 3) & 7;
    int it = (bid >> 6) & 7;
    int b  = bid >> 9;
    int i0 = it * 16, j0 = jt * 16;
    int tid = threadIdx.x;

    if (tid < 64)
        ((float4*)Vsh)[tid] = ((const float4*)(Vw + c * HH))[tid];

    // stage negated-P and R tiles: 16 rows each, 8 threads/row
    {
        int rr = tid >> 3;             // 0..15
        int c8 = tid & 7;
        int gi = i0 + rr;
        int gj = j0 + rr;
        const float* srcR = &g_cumm[((size_t)(b * SS + gj) * CC + c) * HH];
        const float* srcP = (gi == 0) ? (const float*)0
            : &g_cumm[((size_t)(b * SS + gi - 1) * CC + c) * HH];
        float* dstR = &Rsh[rr * PAD];
        float* dstP = &Psh[rr * PAD];
#pragma unroll
        for (int k = 0; k < 8; k++) {
            int h = c8 * 4 + k * 32;
            *(float4*)&dstR[h] = *(const float4*)&srcR[h];
            float4 pv = srcP ? *(const float4*)&srcP[h]
                             : make_float4(0.f, 0.f, 0.f, 0.f);
            pv.x = -pv.x; pv.y = -pv.y; pv.z = -pv.z; pv.w = -pv.w;
            *(float4*)&dstP[h] = pv;
        }
    }
    __syncthreads();

    // epilogue operands loaded EARLY
    float cej[2], cei[2];
#pragma unroll
    for (int rep = 0; rep < 2; rep++) {
        int idx = tid + rep * 128;
        int gie = i0 + (idx >> 4), gje = j0 + (idx & 15);
        cej[rep] = g_cumexp[(b * SS + gje) * CC + c];
        cei[rep] = (gie > 0) ? g_cumexp[(b * SS + gie - 1) * CC + c] : 0.0f;
    }
    float vb = Vb[c];

    int lane = tid & 31;
    int hq = tid >> 5;                 // h quarter 0..3
    int ilane = lane & 7;              // 0..7  (phase-major)
    int jlane = lane >> 3;             // 0..3

    F2U acc[2][4];
#pragma unroll
    for (int ii = 0; ii < 2; ii++)
#pragma unroll
        for (int jj = 0; jj < 4; jj++) {
            acc[ii][jj].f.x = 0.0f;
            acc[ii][jj].f.y = 0.0f;
        }

    int hbase = hq * 64;
#pragma unroll 4
    for (int hh = 0; hh < 64; hh += 4) {
        int h = hbase + hh;
        float4 v  = *(const float4*)&Vsh[h];
        float4 p0 = *(const float4*)&Psh[ilane * PAD + h];
        float4 p1 = *(const float4*)&Psh[(ilane + 8) * PAD + h];
        F2U v01, v23, p0a, p0b, p1a, p1b;
        v01.f = make_float2(v.x, v.y);   v23.f = make_float2(v.z, v.w);
        p0a.f = make_float2(p0.x, p0.y); p0b.f = make_float2(p0.z, p0.w);
        p1a.f = make_float2(p1.x, p1.y); p1b.f = make_float2(p1.z, p1.w);
#pragma unroll
        for (int jj = 0; jj < 4; jj++) {
            float4 r = *(const float4*)&Rsh[(jlane + 4 * jj) * PAD + h];
            F2U r01, r23, t;
            r01.f = make_float2(r.x, r.y);
            r23.f = make_float2(r.z, r.w);
            pk_add(t, r01, p0a);
            t.f.x = fmaxf(t.f.x, 0.0f); t.f.y = fmaxf(t.f.y, 0.0f);
            pk_fma(acc[0][jj], t, v01, acc[0][jj]);
            pk_add(t, r23, p0b);
            t.f.x = fmaxf(t.f.x, 0.0f); t.f.y = fmaxf(t.f.y, 0.0f);
            pk_fma(acc[0][jj], t, v23, acc[0][jj]);
            pk_add(t, r01, p1a);
            t.f.x = fmaxf(t.f.x, 0.0f); t.f.y = fmaxf(t.f.y, 0.0f);
            pk_fma(acc[1][jj], t, v01, acc[1][jj]);
            pk_add(t, r23, p1b);
            t.f.x = fmaxf(t.f.x, 0.0f); t.f.y = fmaxf(t.f.y, 0.0f);
            pk_fma(acc[1][jj], t, v23, acc[1][jj]);
        }
    }

    __syncthreads();   // all warps done reading Psh before red overwrites it

#pragma unroll
    for (int ii = 0; ii < 2; ii++)
#pragma unroll
        for (int jj = 0; jj < 4; jj++) {
            int i = ilane + 8 * ii;
            int j = jlane + 4 * jj;
            red[hq * 264 + i * 16 + j] = acc[ii][jj].f.x + acc[ii][jj].f.y;
        }
    __syncthreads();

#pragma unroll
    for (int rep = 0; rep < 2; rep++) {
        int idx = tid + rep * 128;
        int i = idx >> 4, j = idx & 15;
        int o = i * 16 + j;
        float s = red[o] + red[264 + o] + red[528 + o] + red[792 + o];
        float d = cej[rep] - cei[rep]; if (d <= 1e-6f) d = 100.0f;
        int gi = i0 + i, gj = j0 + j;
        out[((size_t)(b * SS + gi) * SS + gj) * CC + c] = __fdividef(s, d) + vb;
    }
}

// ---------------------------------------------------------------------------
extern "C" void kernel_launch(void* const* d_in, const int* in_sizes, int n_in,
                              void* d_out, int out_size)
{
    (void)in_sizes; (void)n_in; (void)out_size;
    const float* memory = (const float*)d_in[0];
    const float* Ww     = (const float*)d_in[1];
    const float* Wb     = (const float*)d_in[2];
    const float* Uw     = (const float*)d_in[3];
    const float* Vw     = (const float*)d_in[4];
    const float* Vb     = (const float*)d_in[5];
    float* out          = (float*)d_out;

    kernelA<<<256, 256>>>(memory, Ww, Wb, Uw);
    kernelB<<<128, 256>>>(memory);
    kernelMain<<<1024, 128>>>(Vw, Vb, out);
}